// round 1
// baseline (speedup 1.0000x reference)
#include <cuda_runtime.h>
#include <math.h>

#define EPS      1e-6f
#define HIT_TOL  1e-3f
#define MIN_LEN  1.2e-6f

#define TRI_STRIDE 13          // 12 floats payload + 1 pad (gcd(13,32)=1 -> conflict-free LDS)
#define MAX_TRI_SM 900         // 900*13*4 = 46800 B static smem

// scratch: per-triangle {v0[3], e1[3], e2[3], n[3]} with stride 13
__device__ float g_tri[10000 * TRI_STRIDE];

struct V3 { float x, y, z; };

__device__ __forceinline__ V3 v3(float x, float y, float z) { V3 r; r.x=x; r.y=y; r.z=z; return r; }
__device__ __forceinline__ V3 vsub(V3 a, V3 b) { return v3(a.x-b.x, a.y-b.y, a.z-b.z); }
__device__ __forceinline__ V3 vadd(V3 a, V3 b) { return v3(a.x+b.x, a.y+b.y, a.z+b.z); }
__device__ __forceinline__ V3 vscale(V3 a, float s) { return v3(a.x*s, a.y*s, a.z*s); }
__device__ __forceinline__ float vdot(V3 a, V3 b) { return a.x*b.x + a.y*b.y + a.z*b.z; }
__device__ __forceinline__ V3 vcross(V3 a, V3 b) {
    return v3(a.y*b.z - a.z*b.y,
              a.z*b.x - a.x*b.z,
              a.x*b.y - a.y*b.x);
}

// ---------------------------------------------------------------------------
// prep: per-triangle v0, e1, e2, unit normal
// ---------------------------------------------------------------------------
__global__ void prep_kernel(const float* __restrict__ mesh_v,
                            const int*   __restrict__ mesh_t,
                            int NF)
{
    int f = blockIdx.x * blockDim.x + threadIdx.x;
    if (f >= NF) return;
    int i0 = mesh_t[3*f+0], i1 = mesh_t[3*f+1], i2 = mesh_t[3*f+2];
    V3 p0 = v3(mesh_v[3*i0], mesh_v[3*i0+1], mesh_v[3*i0+2]);
    V3 p1 = v3(mesh_v[3*i1], mesh_v[3*i1+1], mesh_v[3*i1+2]);
    V3 p2 = v3(mesh_v[3*i2], mesh_v[3*i2+1], mesh_v[3*i2+2]);
    V3 e1 = vsub(p1, p0);
    V3 e2 = vsub(p2, p0);
    V3 fn = vcross(e1, e2);
    float inv = 1.0f / sqrtf(vdot(fn, fn));
    V3 n = vscale(fn, inv);
    float* td = g_tri + (size_t)f * TRI_STRIDE;
    td[0]=p0.x; td[1]=p0.y;  td[2]=p0.z;
    td[3]=e1.x; td[4]=e1.y;  td[5]=e1.z;
    td[6]=e2.x; td[7]=e2.y;  td[8]=e2.z;
    td[9]=n.x;  td[10]=n.y;  td[11]=n.z;
    td[12]=0.f;
}

// Moller-Trumbore, mirroring the reference's exact predicate structure.
// Returns hit flag; writes t (ray parameter).
__device__ __forceinline__ bool mt_hit(V3 ro, V3 rd, const float* __restrict__ td, float& t_out)
{
    V3 tv0 = v3(td[0], td[1], td[2]);
    V3 e1  = v3(td[3], td[4], td[5]);
    V3 e2  = v3(td[6], td[7], td[8]);
    V3 h = vcross(rd, e2);
    float a = vdot(e1, h);
    bool cond_a = fabsf(a) < EPS;
    float f = cond_a ? 0.0f : (1.0f / a);
    V3 s = vsub(ro, tv0);
    float u = f * vdot(s, h);
    V3 q = vcross(s, e1);
    float v = f * vdot(rd, q);
    float t = f * vdot(e2, q);
    t_out = t;
    return (!cond_a) && (u >= 0.0f) && (u <= 1.0f) && (v >= 0.0f) && (u + v <= 1.0f) && (t > EPS);
}

// ---------------------------------------------------------------------------
// main kernel: one warp per (t, r, p) path
// ---------------------------------------------------------------------------
__global__ void __launch_bounds__(256)
paths_kernel(const float* __restrict__ tx_v,
             const float* __restrict__ rx_v,
             const int*   __restrict__ pc,
             float*       __restrict__ out,
             int T, int R, int P, int NF)
{
    __shared__ float s_tri[MAX_TRI_SM * TRI_STRIDE];

    const bool use_sm = (NF <= MAX_TRI_SM);
    if (use_sm) {
        for (int i = threadIdx.x; i < NF * TRI_STRIDE; i += blockDim.x)
            s_tri[i] = g_tri[i];
    }
    __syncthreads();
    const float* __restrict__ tbl = use_sm ? s_tri : g_tri;

    const int nPaths = T * R * P;
    const int warp = (blockIdx.x * blockDim.x + threadIdx.x) >> 5;
    const int lane = threadIdx.x & 31;
    if (warp >= nPaths) return;

    // decode (t, r, p) -- row-major (T, R, P)
    const int t_idx = warp / (R * P);
    const int rem   = warp - t_idx * (R * P);
    const int r_idx = rem / P;
    const int p_idx = rem - r_idx * P;

    const int f0 = pc[2 * p_idx + 0];
    const int f1 = pc[2 * p_idx + 1];

    const float* __restrict__ td0 = tbl + f0 * TRI_STRIDE;
    const float* __restrict__ td1 = tbl + f1 * TRI_STRIDE;

    V3 txv = v3(tx_v[3*t_idx], tx_v[3*t_idx+1], tx_v[3*t_idx+2]);
    V3 rxv = v3(rx_v[3*r_idx], rx_v[3*r_idx+1], rx_v[3*r_idx+2]);

    V3 mv0 = v3(td0[0], td0[1], td0[2]);
    V3 n0  = v3(td0[9], td0[10], td0[11]);
    V3 mv1 = v3(td1[0], td1[1], td1[2]);
    V3 n1  = v3(td1[9], td1[10], td1[11]);

    // forward scan: images
    V3 img0 = vsub(txv, vscale(n0, 2.0f * vdot(vsub(txv, mv0), n0)));
    V3 img1 = vsub(img0, vscale(n1, 2.0f * vdot(vsub(img0, mv1), n1)));

    // backward scan: reflection points
    // i = 1 (carry = rx)
    V3 u1 = vsub(rxv, img1);
    float un1 = vdot(u1, n1);
    float vn1 = vdot(vsub(img1, mv1), n1);
    float tt1 = (un1 == 0.0f) ? 0.0f : (-vn1 / un1);
    V3 p1v = vadd(img1, vscale(u1, tt1));
    // i = 0 (carry = p1)
    V3 u0 = vsub(p1v, img0);
    float un0 = vdot(u0, n0);
    float vn0 = vdot(vsub(img0, mv0), n0);
    float tt0 = (un0 == 0.0f) ? 0.0f : (-vn0 / un0);
    V3 p0v = vadd(img0, vscale(u0, tt0));

    // full path: tx, p0, p1, rx ; segment directions
    V3 rd0 = vsub(p0v, txv);
    V3 rd1 = vsub(p1v, p0v);
    V3 rd2 = vsub(rxv, p1v);

    // too_small
    bool too_small = (vdot(rd0, rd0) < MIN_LEN) ||
                     (vdot(rd1, rd1) < MIN_LEN) ||
                     (vdot(rd2, rd2) < MIN_LEN);

    // inside: segment i must hit mirror triangle i
    float tdum;
    bool inside = mt_hit(txv, rd0, td0, tdum) && mt_hit(p0v, rd1, td1, tdum);

    // valid reflections: points on consistent sides of each mirror plane
    float dp0 = vdot(vsub(txv, mv0), n0);
    float dn0 = vdot(vsub(p1v, mv0), n0);
    float dp1 = vdot(vsub(p0v, mv1), n1);
    float dn1 = vdot(vsub(rxv, mv1), n1);
    bool valid_refl = (dp0 * dn0 >= 0.0f) && (dp1 * dn1 >= 0.0f);

    bool premask = inside && valid_refl && !too_small;  // warp-uniform

    // blocked: any mesh triangle hit by any segment with t < 1 - HIT_TOL
    bool blocked = false;
    if (premask) {
        const float lim = 1.0f - HIT_TOL;
        for (int base = 0; base < NF; base += 32) {
            int f = base + lane;
            bool b = false;
            if (f < NF) {
                const float* td = tbl + f * TRI_STRIDE;
                float th;
                if (mt_hit(txv, rd0, td, th) && th < lim) b = true;
                if (!b && mt_hit(p0v, rd1, td, th) && th < lim) b = true;
                if (!b && mt_hit(p1v, rd2, td, th) && th < lim) b = true;
            }
            if (__any_sync(0xFFFFFFFFu, b)) { blocked = true; break; }
        }
    }

    bool mask = premask && !blocked;

    // ---- outputs (float32): full_paths | objects | mask ----
    if (lane == 0) {
        float* fp = out + (size_t)warp * 12;
        fp[0]=txv.x; fp[1]=txv.y; fp[2]=txv.z;
        fp[3]=p0v.x; fp[4]=p0v.y; fp[5]=p0v.z;
        fp[6]=p1v.x; fp[7]=p1v.y; fp[8]=p1v.z;
        fp[9]=rxv.x; fp[10]=rxv.y; fp[11]=rxv.z;

        float* ob = out + (size_t)nPaths * 12 + (size_t)warp * 4;
        ob[0] = (float)t_idx;
        ob[1] = (float)f0;
        ob[2] = (float)f1;
        ob[3] = (float)r_idx;

        out[(size_t)nPaths * 16 + warp] = mask ? 1.0f : 0.0f;
    }
}

// ---------------------------------------------------------------------------
extern "C" void kernel_launch(void* const* d_in, const int* in_sizes, int n_in,
                              void* d_out, int out_size)
{
    const float* mesh_v = (const float*)d_in[0];   // (NV, 3) f32
    const int*   mesh_t = (const int*)  d_in[1];   // (NF, 3) i32
    const float* tx_v   = (const float*)d_in[2];   // (T, 3)  f32
    const float* rx_v   = (const float*)d_in[3];   // (R, 3)  f32
    const int*   pc     = (const int*)  d_in[4];   // (P, 2)  i32

    const int NF = in_sizes[1] / 3;
    const int T  = in_sizes[2] / 3;
    const int R  = in_sizes[3] / 3;
    const int P  = in_sizes[4] / 2;   // ORDER = 2

    prep_kernel<<<(NF + 127) / 128, 128>>>(mesh_v, mesh_t, NF);

    const int nPaths = T * R * P;
    const int warpsPerBlock = 8;                    // 256 threads
    const int blocks = (nPaths + warpsPerBlock - 1) / warpsPerBlock;
    paths_kernel<<<blocks, 256>>>(tx_v, rx_v, pc, (float*)d_out, T, R, P, NF);
}

// round 2
// speedup vs baseline: 1.2917x; 1.2917x over previous
#include <cuda_runtime.h>
#include <math.h>

#define EPS      1e-6f
#define HIT_TOL  1e-3f
#define MIN_LEN  1.2e-6f

#define TRI_STRIDE 12          // 12 floats = 3 x float4, 48B (16B-aligned)
#define MAX_PATHS  16384

// per-triangle {v0[3], e1[3], e2[3], n[3]}  (3 float4 each)
__device__ float4 g_tri[10000 * 3];
__device__ int    g_queue[MAX_PATHS];
__device__ int    g_count;

struct V3 { float x, y, z; };

__device__ __forceinline__ V3 v3(float x, float y, float z) { V3 r; r.x=x; r.y=y; r.z=z; return r; }
__device__ __forceinline__ V3 vsub(V3 a, V3 b) { return v3(a.x-b.x, a.y-b.y, a.z-b.z); }
__device__ __forceinline__ V3 vadd(V3 a, V3 b) { return v3(a.x+b.x, a.y+b.y, a.z+b.z); }
__device__ __forceinline__ V3 vscale(V3 a, float s) { return v3(a.x*s, a.y*s, a.z*s); }
__device__ __forceinline__ float vdot(V3 a, V3 b) { return a.x*b.x + a.y*b.y + a.z*b.z; }
__device__ __forceinline__ V3 vcross(V3 a, V3 b) {
    return v3(a.y*b.z - a.z*b.y,
              a.z*b.x - a.x*b.z,
              a.x*b.y - a.y*b.x);
}

struct Tri { V3 v0, e1, e2, n; };

__device__ __forceinline__ Tri load_tri(int f) {
    const float4* p = g_tri + f * 3;
    float4 q0 = p[0], q1 = p[1], q2 = p[2];
    Tri t;
    t.v0 = v3(q0.x, q0.y, q0.z);
    t.e1 = v3(q0.w, q1.x, q1.y);
    t.e2 = v3(q1.z, q1.w, q2.x);
    t.n  = v3(q2.y, q2.z, q2.w);
    return t;
}

// Moller-Trumbore, mirroring the reference's exact predicate structure.
__device__ __forceinline__ bool mt_hit(V3 ro, V3 rd, const Tri& T, float& t_out)
{
    V3 h = vcross(rd, T.e2);
    float a = vdot(T.e1, h);
    bool cond_a = fabsf(a) < EPS;
    float f = cond_a ? 0.0f : (1.0f / a);
    V3 s = vsub(ro, T.v0);
    float u = f * vdot(s, h);
    V3 q = vcross(s, T.e1);
    float v = f * vdot(rd, q);
    float t = f * vdot(T.e2, q);
    t_out = t;
    return (!cond_a) && (u >= 0.0f) && (u <= 1.0f) && (v >= 0.0f) && (u + v <= 1.0f) && (t > EPS);
}

// ---------------------------------------------------------------------------
// prep: per-triangle v0, e1, e2, unit normal ; also resets the queue counter
// ---------------------------------------------------------------------------
__global__ void prep_kernel(const float* __restrict__ mesh_v,
                            const int*   __restrict__ mesh_t,
                            int NF)
{
    int f = blockIdx.x * blockDim.x + threadIdx.x;
    if (f == 0) g_count = 0;
    if (f >= NF) return;
    int i0 = mesh_t[3*f+0], i1 = mesh_t[3*f+1], i2 = mesh_t[3*f+2];
    V3 p0 = v3(mesh_v[3*i0], mesh_v[3*i0+1], mesh_v[3*i0+2]);
    V3 p1 = v3(mesh_v[3*i1], mesh_v[3*i1+1], mesh_v[3*i1+2]);
    V3 p2 = v3(mesh_v[3*i2], mesh_v[3*i2+1], mesh_v[3*i2+2]);
    V3 e1 = vsub(p1, p0);
    V3 e2 = vsub(p2, p0);
    V3 fn = vcross(e1, e2);
    float inv = 1.0f / sqrtf(vdot(fn, fn));
    V3 n = vscale(fn, inv);
    float4* td = g_tri + f * 3;
    td[0] = make_float4(p0.x, p0.y, p0.z, e1.x);
    td[1] = make_float4(e1.y, e1.z, e2.x, e2.y);
    td[2] = make_float4(e2.z, n.x, n.y, n.z);
}

// ---------------------------------------------------------------------------
// Phase A: one THREAD per (t, r, p) path. Path math + premask + all outputs.
// Survivors (premask true) are queued for occlusion testing.
// ---------------------------------------------------------------------------
__global__ void __launch_bounds__(256)
paths_kernel(const float* __restrict__ tx_v,
             const float* __restrict__ rx_v,
             const int*   __restrict__ pc,
             float*       __restrict__ out,
             int T, int R, int P)
{
    const int nPaths = T * R * P;
    const int idx = blockIdx.x * blockDim.x + threadIdx.x;
    if (idx >= nPaths) return;

    // decode (t, r, p) -- row-major (T, R, P)
    const int t_idx = idx / (R * P);
    const int rem   = idx - t_idx * (R * P);
    const int r_idx = rem / P;
    const int p_idx = rem - r_idx * P;

    const int f0 = pc[2 * p_idx + 0];
    const int f1 = pc[2 * p_idx + 1];

    Tri T0 = load_tri(f0);
    Tri T1 = load_tri(f1);

    V3 txv = v3(tx_v[3*t_idx], tx_v[3*t_idx+1], tx_v[3*t_idx+2]);
    V3 rxv = v3(rx_v[3*r_idx], rx_v[3*r_idx+1], rx_v[3*r_idx+2]);

    V3 mv0 = T0.v0, n0 = T0.n;
    V3 mv1 = T1.v0, n1 = T1.n;

    // forward scan: images
    V3 img0 = vsub(txv, vscale(n0, 2.0f * vdot(vsub(txv, mv0), n0)));
    V3 img1 = vsub(img0, vscale(n1, 2.0f * vdot(vsub(img0, mv1), n1)));

    // backward scan: reflection points
    V3 u1 = vsub(rxv, img1);
    float un1 = vdot(u1, n1);
    float vn1 = vdot(vsub(img1, mv1), n1);
    float tt1 = (un1 == 0.0f) ? 0.0f : (-vn1 / un1);
    V3 p1v = vadd(img1, vscale(u1, tt1));

    V3 u0 = vsub(p1v, img0);
    float un0 = vdot(u0, n0);
    float vn0 = vdot(vsub(img0, mv0), n0);
    float tt0 = (un0 == 0.0f) ? 0.0f : (-vn0 / un0);
    V3 p0v = vadd(img0, vscale(u0, tt0));

    // segments
    V3 rd0 = vsub(p0v, txv);
    V3 rd1 = vsub(p1v, p0v);
    V3 rd2 = vsub(rxv, p1v);

    bool too_small = (vdot(rd0, rd0) < MIN_LEN) ||
                     (vdot(rd1, rd1) < MIN_LEN) ||
                     (vdot(rd2, rd2) < MIN_LEN);

    float tdum;
    bool inside = mt_hit(txv, rd0, T0, tdum) && mt_hit(p0v, rd1, T1, tdum);

    float dp0 = vdot(vsub(txv, mv0), n0);
    float dn0 = vdot(vsub(p1v, mv0), n0);
    float dp1 = vdot(vsub(p0v, mv1), n1);
    float dn1 = vdot(vsub(rxv, mv1), n1);
    bool valid_refl = (dp0 * dn0 >= 0.0f) && (dp1 * dn1 >= 0.0f);

    bool premask = inside && valid_refl && !too_small;

    // outputs: full_paths | objects(float) | mask
    float* fp = out + (size_t)idx * 12;
    ((float4*)fp)[0] = make_float4(txv.x, txv.y, txv.z, p0v.x);
    ((float4*)fp)[1] = make_float4(p0v.y, p0v.z, p1v.x, p1v.y);
    ((float4*)fp)[2] = make_float4(p1v.z, rxv.x, rxv.y, rxv.z);

    float* ob = out + (size_t)nPaths * 12 + (size_t)idx * 4;
    ((float4*)ob)[0] = make_float4((float)t_idx, (float)f0, (float)f1, (float)r_idx);

    out[(size_t)nPaths * 16 + idx] = premask ? 1.0f : 0.0f;

    if (premask) {
        int slot = atomicAdd(&g_count, 1);
        g_queue[slot] = idx;
    }
}

// ---------------------------------------------------------------------------
// Phase B: one WARP per surviving path; lane-parallel occlusion with early exit.
// Fixed grid, grid-stride over the queue (graph-capture safe).
// ---------------------------------------------------------------------------
__global__ void __launch_bounds__(256)
occlusion_kernel(float* __restrict__ out, int nPaths, int NF)
{
    const int S = g_count;
    if (S == 0) return;

    const int lane       = threadIdx.x & 31;
    const int warpLocal  = threadIdx.x >> 5;
    const int warpGlobal = blockIdx.x * (blockDim.x >> 5) + warpLocal;
    const int totalWarps = gridDim.x * (blockDim.x >> 5);

    const float lim = 1.0f - HIT_TOL;

    for (int s = warpGlobal; s < S; s += totalWarps) {
        const int idx = g_queue[s];
        const float* fp = out + (size_t)idx * 12;
        V3 txv = v3(fp[0], fp[1], fp[2]);
        V3 p0v = v3(fp[3], fp[4], fp[5]);
        V3 p1v = v3(fp[6], fp[7], fp[8]);
        V3 rxv = v3(fp[9], fp[10], fp[11]);
        V3 rd0 = vsub(p0v, txv);
        V3 rd1 = vsub(p1v, p0v);
        V3 rd2 = vsub(rxv, p1v);

        bool blocked = false;
        for (int base = 0; base < NF; base += 32) {
            int f = base + lane;
            bool b = false;
            if (f < NF) {
                Tri Tt = load_tri(f);
                float th;
                if (mt_hit(txv, rd0, Tt, th) && th < lim) b = true;
                if (!b && mt_hit(p0v, rd1, Tt, th) && th < lim) b = true;
                if (!b && mt_hit(p1v, rd2, Tt, th) && th < lim) b = true;
            }
            if (__any_sync(0xFFFFFFFFu, b)) { blocked = true; break; }
        }

        if (blocked && lane == 0)
            out[(size_t)nPaths * 16 + idx] = 0.0f;
    }
}

// ---------------------------------------------------------------------------
extern "C" void kernel_launch(void* const* d_in, const int* in_sizes, int n_in,
                              void* d_out, int out_size)
{
    const float* mesh_v = (const float*)d_in[0];   // (NV, 3) f32
    const int*   mesh_t = (const int*)  d_in[1];   // (NF, 3) i32
    const float* tx_v   = (const float*)d_in[2];   // (T, 3)  f32
    const float* rx_v   = (const float*)d_in[3];   // (R, 3)  f32
    const int*   pc     = (const int*)  d_in[4];   // (P, 2)  i32

    const int NF = in_sizes[1] / 3;
    const int T  = in_sizes[2] / 3;
    const int R  = in_sizes[3] / 3;
    const int P  = in_sizes[4] / 2;   // ORDER = 2

    prep_kernel<<<(NF + 127) / 128, 128>>>(mesh_v, mesh_t, NF);

    const int nPaths = T * R * P;
    const int blocksA = (nPaths + 255) / 256;
    paths_kernel<<<blocksA, 256>>>(tx_v, rx_v, pc, (float*)d_out, T, R, P);

    occlusion_kernel<<<64, 256>>>((float*)d_out, nPaths, NF);
}

// round 3
// speedup vs baseline: 1.8821x; 1.4571x over previous
#include <cuda_runtime.h>
#include <math.h>

#define EPS      1e-6f
#define HIT_TOL  1e-3f
#define MIN_LEN  1.2e-6f

struct V3 { float x, y, z; };

__device__ __forceinline__ V3 v3(float x, float y, float z) { V3 r; r.x=x; r.y=y; r.z=z; return r; }
__device__ __forceinline__ V3 vsub(V3 a, V3 b) { return v3(a.x-b.x, a.y-b.y, a.z-b.z); }
__device__ __forceinline__ V3 vadd(V3 a, V3 b) { return v3(a.x+b.x, a.y+b.y, a.z+b.z); }
__device__ __forceinline__ V3 vscale(V3 a, float s) { return v3(a.x*s, a.y*s, a.z*s); }
__device__ __forceinline__ float vdot(V3 a, V3 b) { return a.x*b.x + a.y*b.y + a.z*b.z; }
__device__ __forceinline__ V3 vcross(V3 a, V3 b) {
    return v3(a.y*b.z - a.z*b.y,
              a.z*b.x - a.x*b.z,
              a.x*b.y - a.y*b.x);
}
__device__ __forceinline__ V3 shfl_v3(V3 v, int src) {
    v.x = __shfl_sync(0xFFFFFFFFu, v.x, src);
    v.y = __shfl_sync(0xFFFFFFFFu, v.y, src);
    v.z = __shfl_sync(0xFFFFFFFFu, v.z, src);
    return v;
}

__device__ __forceinline__ V3 load_vert(const float* __restrict__ mv, int i) {
    return v3(__ldg(mv + 3*i), __ldg(mv + 3*i + 1), __ldg(mv + 3*i + 2));
}

struct Tri { V3 v0, e1, e2; };

__device__ __forceinline__ Tri load_tri(const float* __restrict__ mesh_v,
                                        const int*   __restrict__ mesh_t,
                                        int f)
{
    int i0 = __ldg(mesh_t + 3*f);
    int i1 = __ldg(mesh_t + 3*f + 1);
    int i2 = __ldg(mesh_t + 3*f + 2);
    V3 p0 = load_vert(mesh_v, i0);
    V3 p1 = load_vert(mesh_v, i1);
    V3 p2 = load_vert(mesh_v, i2);
    Tri t;
    t.v0 = p0;
    t.e1 = vsub(p1, p0);
    t.e2 = vsub(p2, p0);
    return t;
}

// Moller-Trumbore, mirroring the reference's exact predicate structure.
__device__ __forceinline__ bool mt_hit(V3 ro, V3 rd, const Tri& T, float& t_out)
{
    V3 h = vcross(rd, T.e2);
    float a = vdot(T.e1, h);
    bool cond_a = fabsf(a) < EPS;
    float f = cond_a ? 0.0f : (1.0f / a);
    V3 s = vsub(ro, T.v0);
    float u = f * vdot(s, h);
    V3 q = vcross(s, T.e1);
    float v = f * vdot(rd, q);
    float t = f * vdot(T.e2, q);
    t_out = t;
    return (!cond_a) && (u >= 0.0f) && (u <= 1.0f) && (v >= 0.0f) && (u + v <= 1.0f) && (t > EPS);
}

// ---------------------------------------------------------------------------
// Single fused kernel: one thread per (t, r, p) path. Path math + premask +
// outputs per thread; rare occlusion tests handled warp-cooperatively.
// ---------------------------------------------------------------------------
__global__ void __launch_bounds__(128)
fused_kernel(const float* __restrict__ mesh_v,
             const int*   __restrict__ mesh_t,
             const float* __restrict__ tx_v,
             const float* __restrict__ rx_v,
             const int*   __restrict__ pc,
             float*       __restrict__ out,
             int T, int R, int P, int NF)
{
    const int nPaths = T * R * P;
    int idx = blockIdx.x * blockDim.x + threadIdx.x;
    const bool valid = (idx < nPaths);
    if (idx >= nPaths) idx = nPaths - 1;       // clamp; keep warp converged
    const int lane = threadIdx.x & 31;

    // decode (t, r, p) -- row-major (T, R, P)
    const int t_idx = idx / (R * P);
    const int rem   = idx - t_idx * (R * P);
    const int r_idx = rem / P;
    const int p_idx = rem - r_idx * P;

    const int f0 = __ldg(pc + 2 * p_idx);
    const int f1 = __ldg(pc + 2 * p_idx + 1);

    Tri T0 = load_tri(mesh_v, mesh_t, f0);
    Tri T1 = load_tri(mesh_v, mesh_t, f1);

    // unit normals (match reference: fn / ||fn||)
    V3 fn0 = vcross(T0.e1, T0.e2);
    V3 n0  = vscale(fn0, 1.0f / sqrtf(vdot(fn0, fn0)));
    V3 fn1 = vcross(T1.e1, T1.e2);
    V3 n1  = vscale(fn1, 1.0f / sqrtf(vdot(fn1, fn1)));

    V3 txv = v3(__ldg(tx_v + 3*t_idx), __ldg(tx_v + 3*t_idx + 1), __ldg(tx_v + 3*t_idx + 2));
    V3 rxv = v3(__ldg(rx_v + 3*r_idx), __ldg(rx_v + 3*r_idx + 1), __ldg(rx_v + 3*r_idx + 2));

    V3 mv0 = T0.v0, mv1 = T1.v0;

    // forward scan: images
    V3 img0 = vsub(txv, vscale(n0, 2.0f * vdot(vsub(txv, mv0), n0)));
    V3 img1 = vsub(img0, vscale(n1, 2.0f * vdot(vsub(img0, mv1), n1)));

    // backward scan: reflection points
    V3 u1 = vsub(rxv, img1);
    float un1 = vdot(u1, n1);
    float vn1 = vdot(vsub(img1, mv1), n1);
    float tt1 = (un1 == 0.0f) ? 0.0f : (-vn1 / un1);
    V3 p1v = vadd(img1, vscale(u1, tt1));

    V3 u0 = vsub(p1v, img0);
    float un0 = vdot(u0, n0);
    float vn0 = vdot(vsub(img0, mv0), n0);
    float tt0 = (un0 == 0.0f) ? 0.0f : (-vn0 / un0);
    V3 p0v = vadd(img0, vscale(u0, tt0));

    // segments
    V3 rd0 = vsub(p0v, txv);
    V3 rd1 = vsub(p1v, p0v);
    V3 rd2 = vsub(rxv, p1v);

    bool too_small = (vdot(rd0, rd0) < MIN_LEN) ||
                     (vdot(rd1, rd1) < MIN_LEN) ||
                     (vdot(rd2, rd2) < MIN_LEN);

    float tdum;
    bool inside = mt_hit(txv, rd0, T0, tdum) && mt_hit(p0v, rd1, T1, tdum);

    float dp0 = vdot(vsub(txv, mv0), n0);
    float dn0 = vdot(vsub(p1v, mv0), n0);
    float dp1 = vdot(vsub(p0v, mv1), n1);
    float dn1 = vdot(vsub(rxv, mv1), n1);
    bool valid_refl = (dp0 * dn0 >= 0.0f) && (dp1 * dn1 >= 0.0f);

    bool premask = inside && valid_refl && !too_small && valid;

    // ---- warp-cooperative occlusion for the rare survivors ----
    bool blocked = false;
    unsigned ball = __ballot_sync(0xFFFFFFFFu, premask);
    const float lim = 1.0f - HIT_TOL;
    while (ball) {
        const int src = __ffs(ball) - 1;
        ball &= ball - 1;
        V3 a0 = shfl_v3(txv, src);
        V3 a1 = shfl_v3(p0v, src);
        V3 a2 = shfl_v3(p1v, src);
        V3 a3 = shfl_v3(rxv, src);
        V3 d0 = vsub(a1, a0);
        V3 d1 = vsub(a2, a1);
        V3 d2 = vsub(a3, a2);

        bool blk = false;
        for (int base = 0; base < NF; base += 32) {
            int f = base + lane;
            bool b = false;
            if (f < NF) {
                Tri Tt = load_tri(mesh_v, mesh_t, f);
                float th;
                if (mt_hit(a0, d0, Tt, th) && th < lim) b = true;
                if (!b && mt_hit(a1, d1, Tt, th) && th < lim) b = true;
                if (!b && mt_hit(a2, d2, Tt, th) && th < lim) b = true;
            }
            if (__any_sync(0xFFFFFFFFu, b)) { blk = true; break; }
        }
        if (lane == src) blocked = blk;
    }

    bool mask = premask && !blocked;

    // ---- outputs (float32): full_paths | objects | mask ----
    if (valid) {
        float* fp = out + (size_t)idx * 12;
        ((float4*)fp)[0] = make_float4(txv.x, txv.y, txv.z, p0v.x);
        ((float4*)fp)[1] = make_float4(p0v.y, p0v.z, p1v.x, p1v.y);
        ((float4*)fp)[2] = make_float4(p1v.z, rxv.x, rxv.y, rxv.z);

        float* ob = out + (size_t)nPaths * 12 + (size_t)idx * 4;
        ((float4*)ob)[0] = make_float4((float)t_idx, (float)f0, (float)f1, (float)r_idx);

        out[(size_t)nPaths * 16 + idx] = mask ? 1.0f : 0.0f;
    }
}

// ---------------------------------------------------------------------------
extern "C" void kernel_launch(void* const* d_in, const int* in_sizes, int n_in,
                              void* d_out, int out_size)
{
    const float* mesh_v = (const float*)d_in[0];   // (NV, 3) f32
    const int*   mesh_t = (const int*)  d_in[1];   // (NF, 3) i32
    const float* tx_v   = (const float*)d_in[2];   // (T, 3)  f32
    const float* rx_v   = (const float*)d_in[3];   // (R, 3)  f32
    const int*   pc     = (const int*)  d_in[4];   // (P, 2)  i32

    const int NF = in_sizes[1] / 3;
    const int T  = in_sizes[2] / 3;
    const int R  = in_sizes[3] / 3;
    const int P  = in_sizes[4] / 2;   // ORDER = 2

    const int nPaths = T * R * P;
    const int threads = 128;
    const int blocks = (nPaths + threads - 1) / threads;
    fused_kernel<<<blocks, threads>>>(mesh_v, mesh_t, tx_v, rx_v, pc,
                                      (float*)d_out, T, R, P, NF);
}